// round 6
// baseline (speedup 1.0000x reference)
#include <cuda_runtime.h>
#include <cuda_fp16.h>
#include <cstdint>
#include <math.h>

#define FD 512
#define RD 196
#define RP 224
#define VDIM 300
#define NI 1000
#define NIPAD 1024
#define NB 256

// ---- smem byte map ----
#define G1_STAGE 56320
#define G1_QH 0
#define G1_QL 10240
#define G1_BH 20480
#define G1_BL 38400
#define P_H   0
#define P_L   59392
#define PSTR  464
#define G2_BASE  118784
#define G2_STAGE 17408
#define G2_LO    8704
#define G2_PITCH 272
#define RED_M 153600
#define RED_S 155648
#define INV_S 157696
#define SMEM_REQ 158720

__device__ __align__(16) __half g_qh[NIPAD * FD];
__device__ __align__(16) __half g_ql[NIPAD * FD];
__device__ __align__(16) __half g_th[(size_t)NB * RP * FD];  // Ht [b][r][f]
__device__ __align__(16) __half g_tl[(size_t)NB * RP * FD];

// ---------------- PTX helpers ----------------
__device__ __forceinline__ uint32_t smem_u32(const void* p) {
    uint32_t a;
    asm("{ .reg .u64 t; cvta.to.shared.u64 t, %1; cvt.u32.u64 %0, t; }" : "=r"(a) : "l"(p));
    return a;
}
__device__ __forceinline__ void cpa16(uint32_t d, const void* s) {
    asm volatile("cp.async.cg.shared.global [%0], [%1], 16;" :: "r"(d), "l"(s));
}
#define CP_COMMIT() asm volatile("cp.async.commit_group;")
__device__ __forceinline__ void ldsm4(uint32_t* r, uint32_t a) {
    asm volatile("ldmatrix.sync.aligned.m8n8.x4.shared.b16 {%0,%1,%2,%3},[%4];"
        : "=r"(r[0]), "=r"(r[1]), "=r"(r[2]), "=r"(r[3]) : "r"(a));
}
__device__ __forceinline__ void ldsm4t(uint32_t* r, uint32_t a) {
    asm volatile("ldmatrix.sync.aligned.m8n8.x4.trans.shared.b16 {%0,%1,%2,%3},[%4];"
        : "=r"(r[0]), "=r"(r[1]), "=r"(r[2]), "=r"(r[3]) : "r"(a));
}
__device__ __forceinline__ void ldsm2(uint32_t* r, uint32_t a) {
    asm volatile("ldmatrix.sync.aligned.m8n8.x2.shared.b16 {%0,%1},[%2];"
        : "=r"(r[0]), "=r"(r[1]) : "r"(a));
}
__device__ __forceinline__ void mma_f32(float* d, const uint32_t* a, uint32_t b0, uint32_t b1) {
    asm volatile("mma.sync.aligned.m16n8k16.row.col.f32.f16.f16.f32 "
        "{%0,%1,%2,%3},{%4,%5,%6,%7},{%8,%9},{%0,%1,%2,%3};"
        : "+f"(d[0]), "+f"(d[1]), "+f"(d[2]), "+f"(d[3])
        : "r"(a[0]), "r"(a[1]), "r"(a[2]), "r"(a[3]), "r"(b0), "r"(b1));
}
__device__ __forceinline__ void mma_f16(uint32_t* d, const uint32_t* a, uint32_t b0, uint32_t b1) {
    asm volatile("mma.sync.aligned.m16n8k16.row.col.f16.f16.f16.f16 "
        "{%0,%1},{%2,%3,%4,%5},{%6,%7},{%0,%1};"
        : "+r"(d[0]), "+r"(d[1])
        : "r"(a[0]), "r"(a[1]), "r"(a[2]), "r"(a[3]), "r"(b0), "r"(b1));
}
__device__ __forceinline__ void split16(float v, __half& h, __half& l) {
    h = __float2half_rn(v);
    l = __float2half_rn(v - __half2float(h));
}
__device__ __forceinline__ uint32_t pack2(__half a, __half b) {
    __half2 t = __halves2half2(a, b);
    return *reinterpret_cast<uint32_t*>(&t);
}
__device__ __forceinline__ void addcorr(float* a4, const uint32_t* c2) {
    float2 f0 = __half22float2(*reinterpret_cast<const __half2*>(&c2[0]));
    float2 f1 = __half22float2(*reinterpret_cast<const __half2*>(&c2[1]));
    a4[0] += f0.x; a4[1] += f0.y; a4[2] += f1.x; a4[3] += f1.y;
}

// ---------------- prep 1: q = vecs @ w_g -> fp16 hi/lo ----------------
__global__ __launch_bounds__(128) void qgemm16(
    const float* __restrict__ vecs, const float* __restrict__ w_g)
{
    __shared__ float vs[8][VDIM];
    const int f = blockIdx.x * 128 + threadIdx.x;
    const int i0 = blockIdx.y * 8;
    for (int e = threadIdx.x; e < 8 * VDIM; e += 128) {
        int ii = e / VDIM, v = e % VDIM, i = i0 + ii;
        vs[ii][v] = (i < NI) ? vecs[i * VDIM + v] : 0.0f;
    }
    __syncthreads();
    float acc[8];
#pragma unroll
    for (int ii = 0; ii < 8; ii++) acc[ii] = 0.0f;
#pragma unroll 4
    for (int v = 0; v < VDIM; v++) {
        float w = w_g[v * FD + f];
#pragma unroll
        for (int ii = 0; ii < 8; ii++) acc[ii] += vs[ii][v] * w;
    }
#pragma unroll
    for (int ii = 0; ii < 8; ii++) {
        __half h, l; split16(acc[ii], h, l);
        size_t o = (size_t)(i0 + ii) * FD + f;
        g_qh[o] = h; g_ql[o] = l;
    }
}

// ---------------- prep 2: split + transpose H -> g_th/g_tl ----------------
__global__ __launch_bounds__(256) void hsplit(const float* __restrict__ h)
{
    __shared__ float t[32][33];
    const int b = blockIdx.z, f0 = blockIdx.y * 32, r0 = blockIdx.x * 32;
    const int tx = threadIdx.x, ty = threadIdx.y;
#pragma unroll
    for (int s = 0; s < 4; s++) {
        int fl = ty + 8 * s, r = r0 + tx;
        t[fl][tx] = (r < RD) ? h[((size_t)b * FD + f0 + fl) * RD + r] : 0.0f;
    }
    __syncthreads();
#pragma unroll
    for (int s = 0; s < 4; s++) {
        int rl = ty + 8 * s;
        float v = t[tx][rl];
        __half hi, lo; split16(v, hi, lo);
        size_t o = ((size_t)b * RP + r0 + rl) * FD + f0 + tx;
        g_th[o] = hi; g_tl[o] = lo;
    }
}

// ---------------- stage loaders (cp.async), 512 threads ----------------
__device__ __forceinline__ void issue_g1(uint32_t sb,
    const __half* qh, const __half* ql, const __half* th, const __half* tl,
    int c, int tid)
{
    const int ko = c * 32;
    if (tid < 512) {
        int row = tid >> 2, cc = tid & 3;
        uint32_t d = sb + G1_QH + row * 80 + cc * 16;
        cpa16(d, qh + row * FD + ko + cc * 8);
        cpa16(d + (G1_QL - G1_QH), ql + row * FD + ko + cc * 8);
    }
    for (int t = tid; t < 896; t += 512) {
        int row = t >> 2, cc = t & 3;
        uint32_t d = sb + G1_BH + row * 80 + cc * 16;
        cpa16(d, th + row * FD + ko + cc * 8);
        cpa16(d + (G1_BL - G1_BH), tl + row * FD + ko + cc * 8);
    }
}
__device__ __forceinline__ void issue_g2(uint32_t sb,
    const __half* th, const __half* tl, int q, int kc, int tid)
{
    const int ro = kc * 32, fo = q * 128;
    if (tid < 512) {
        int row = tid >> 4, cc = tid & 15;
        size_t g = (size_t)(ro + row) * FD + fo + cc * 8;
        uint32_t d = sb + row * G2_PITCH + cc * 16;
        cpa16(d, th + g);
        cpa16(d + G2_LO, tl + g);
    }
}

// ---------------- main fused kernel: 512 threads, 16 warps ----------------
__global__ __launch_bounds__(512, 1) void fused_mma(float* __restrict__ out)
{
    extern __shared__ char sm[];
    const uint32_t sbase = smem_u32(sm);
    float* redm = reinterpret_cast<float*>(sm + RED_M);
    float* reds = reinterpret_cast<float*>(sm + RED_S);
    float* invs = reinterpret_cast<float*>(sm + INV_S);

    const int tid = threadIdx.x, lane = tid & 31, wid = tid >> 5;
    const int mw = wid >> 2, nw = wid & 3;       // 4 x 4 warp grid
    const int b = blockIdx.y, i0 = blockIdx.x * 128;

    const __half* qh = g_qh + (size_t)i0 * FD;
    const __half* ql = g_ql + (size_t)i0 * FD;
    const __half* th = g_th + (size_t)b * RP * FD;
    const __half* tl = g_tl + (size_t)b * RP * FD;

    const int arow = (lane & 7) + ((lane >> 3) & 1) * 8;
    const int acg  = (lane >> 4) * 16;

    // ======== GEMM1: C[128 i][224 r], K=512; warp tile 32 x 56 ========
    float acc[2][7][4];
    uint32_t cor[2][7][2];
#pragma unroll
    for (int mf = 0; mf < 2; mf++)
#pragma unroll
        for (int nf = 0; nf < 7; nf++) {
#pragma unroll
            for (int e = 0; e < 4; e++) acc[mf][nf][e] = 0.0f;
            cor[mf][nf][0] = 0u; cor[mf][nf][1] = 0u;
        }

    issue_g1(sbase, qh, ql, th, tl, 0, tid);
    CP_COMMIT();
    for (int c = 0; c < 16; c++) {
        const uint32_t st = sbase + (uint32_t)(c & 1) * G1_STAGE;
        if (c < 15) {
            issue_g1(sbase + (uint32_t)((c + 1) & 1) * G1_STAGE, qh, ql, th, tl, c + 1, tid);
            CP_COMMIT();
            asm volatile("cp.async.wait_group 1;");
        } else {
            asm volatile("cp.async.wait_group 0;");
        }
        __syncthreads();
#pragma unroll
        for (int kk = 0; kk < 2; kk++) {
            uint32_t ah[2][4], al[2][4];
#pragma unroll
            for (int mf = 0; mf < 2; mf++) {
                uint32_t ad = st + G1_QH + (uint32_t)(mw * 32 + mf * 16 + arow) * 80 + kk * 32 + acg;
                ldsm4(ah[mf], ad);
                ldsm4(al[mf], ad + (G1_QL - G1_QH));
            }
#pragma unroll
            for (int p = 0; p < 3; p++) {
                uint32_t bd = st + G1_BH + (uint32_t)(nw * 56 + p * 16 + arow) * 80 + kk * 32 + acg;
                uint32_t bh[4], bl[4];
                ldsm4(bh, bd);
                ldsm4(bl, bd + (G1_BL - G1_BH));
#pragma unroll
                for (int mf = 0; mf < 2; mf++) {
                    mma_f32(acc[mf][2 * p],     ah[mf], bh[0], bh[2]);
                    mma_f32(acc[mf][2 * p + 1], ah[mf], bh[1], bh[3]);
                    mma_f16(cor[mf][2 * p],     al[mf], bh[0], bh[2]);
                    mma_f16(cor[mf][2 * p + 1], al[mf], bh[1], bh[3]);
                    mma_f16(cor[mf][2 * p],     ah[mf], bl[0], bl[2]);
                    mma_f16(cor[mf][2 * p + 1], ah[mf], bl[1], bl[3]);
                }
            }
            {
                uint32_t bd = st + G1_BH + (uint32_t)(nw * 56 + 48 + (lane & 7)) * 80
                              + kk * 32 + ((lane >> 3) & 1) * 16;
                uint32_t bh[2], bl[2];
                ldsm2(bh, bd);
                ldsm2(bl, bd + (G1_BL - G1_BH));
#pragma unroll
                for (int mf = 0; mf < 2; mf++) {
                    mma_f32(acc[mf][6], ah[mf], bh[0], bh[1]);
                    mma_f16(cor[mf][6], al[mf], bh[0], bh[1]);
                    mma_f16(cor[mf][6], ah[mf], bl[0], bl[1]);
                }
            }
        }
        __syncthreads();
    }
#pragma unroll
    for (int mf = 0; mf < 2; mf++)
#pragma unroll
        for (int nf = 0; nf < 7; nf++) addcorr(acc[mf][nf], cor[mf][nf]);

    // ======== softmax over r ========
    const int qlane = lane >> 2, plane = 2 * (lane & 3);
#pragma unroll
    for (int mf = 0; mf < 2; mf++)
#pragma unroll
        for (int hh = 0; hh < 2; hh++) {
            float m = -INFINITY;
#pragma unroll
            for (int nf = 0; nf < 7; nf++)
#pragma unroll
                for (int e = 0; e < 2; e++) {
                    int col = nw * 56 + nf * 8 + plane + e;
                    if (col < RD) m = fmaxf(m, acc[mf][nf][2 * hh + e]);
                }
            m = fmaxf(m, __shfl_xor_sync(0xffffffffu, m, 1));
            m = fmaxf(m, __shfl_xor_sync(0xffffffffu, m, 2));
            if ((lane & 3) == 0) {
                int row = mw * 32 + mf * 16 + qlane + hh * 8;
                redm[row * 4 + nw] = m;
            }
        }
    __syncthreads();
#pragma unroll
    for (int mf = 0; mf < 2; mf++)
#pragma unroll
        for (int hh = 0; hh < 2; hh++) {
            int row = mw * 32 + mf * 16 + qlane + hh * 8;
            float m = fmaxf(fmaxf(redm[row * 4], redm[row * 4 + 1]),
                            fmaxf(redm[row * 4 + 2], redm[row * 4 + 3]));
            float s = 0.0f;
#pragma unroll
            for (int nf = 0; nf < 7; nf++) {
                float v0 = 0.0f, v1 = 0.0f;
                int col = nw * 56 + nf * 8 + plane;
                if (col     < RD) { v0 = __expf(acc[mf][nf][2 * hh]     - m); s += v0; }
                if (col + 1 < RD) { v1 = __expf(acc[mf][nf][2 * hh + 1] - m); s += v1; }
                __half h0, l0, h1, l1;
                split16(v0, h0, l0); split16(v1, h1, l1);
                uint32_t off = (uint32_t)row * PSTR + (uint32_t)col * 2;
                *reinterpret_cast<uint32_t*>(sm + P_H + off) = pack2(h0, h1);
                *reinterpret_cast<uint32_t*>(sm + P_L + off) = pack2(l0, l1);
            }
            s += __shfl_xor_sync(0xffffffffu, s, 1);
            s += __shfl_xor_sync(0xffffffffu, s, 2);
            if ((lane & 3) == 0) reds[row * 4 + nw] = s;
        }
    __syncthreads();
    if (wid < 4) {
        int row = wid * 32 + lane;
        float t = reds[row * 4] + reds[row * 4 + 1] + reds[row * 4 + 2] + reds[row * 4 + 3];
        invs[row] = 1.0f / t;
    }
    __syncthreads();

    // ======== GEMM2: E[128 i][512 f], K=224; warp tile 32 x 32 ========
    const int brow = lane & 15;
    const int bcg  = (lane >> 4) * 16;
    for (int q = 0; q < 4; q++) {
        float acc2[2][4][4];
        uint32_t cor2[2][4][2];
#pragma unroll
        for (int mf = 0; mf < 2; mf++)
#pragma unroll
            for (int nf = 0; nf < 4; nf++) {
#pragma unroll
                for (int e = 0; e < 4; e++) acc2[mf][nf][e] = 0.0f;
                cor2[mf][nf][0] = 0u; cor2[mf][nf][1] = 0u;
            }

        issue_g2(sbase + G2_BASE, th, tl, q, 0, tid);
        CP_COMMIT();
        for (int kc = 0; kc < 7; kc++) {
            const uint32_t st = sbase + G2_BASE + (uint32_t)(kc & 1) * G2_STAGE;
            if (kc < 6) {
                issue_g2(sbase + G2_BASE + (uint32_t)((kc + 1) & 1) * G2_STAGE, th, tl, q, kc + 1, tid);
                CP_COMMIT();
                asm volatile("cp.async.wait_group 1;");
            } else {
                asm volatile("cp.async.wait_group 0;");
            }
            __syncthreads();
#pragma unroll
            for (int kk = 0; kk < 2; kk++) {
                uint32_t ah[2][4], al[2][4];
#pragma unroll
                for (int mf = 0; mf < 2; mf++) {
                    uint32_t ad = sbase + P_H + (uint32_t)(mw * 32 + mf * 16 + arow) * PSTR
                                  + (uint32_t)(kc * 64 + kk * 32) + acg;
                    ldsm4(ah[mf], ad);
                    ldsm4(al[mf], ad + (P_L - P_H));
                }
#pragma unroll
                for (int p = 0; p < 2; p++) {
                    uint32_t bd = st + (uint32_t)(kk * 16 + brow) * G2_PITCH
                                  + (uint32_t)(nw * 64 + p * 32) + bcg;
                    uint32_t bh[4], bl[4];
                    ldsm4t(bh, bd);
                    ldsm4t(bl, bd + G2_LO);
#pragma unroll
                    for (int mf = 0; mf < 2; mf++) {
                        mma_f32(acc2[mf][2 * p],     ah[mf], bh[0], bh[1]);
                        mma_f32(acc2[mf][2 * p + 1], ah[mf], bh[2], bh[3]);
                        mma_f16(cor2[mf][2 * p],     al[mf], bh[0], bh[1]);
                        mma_f16(cor2[mf][2 * p + 1], al[mf], bh[2], bh[3]);
                        mma_f16(cor2[mf][2 * p],     ah[mf], bl[0], bl[1]);
                        mma_f16(cor2[mf][2 * p + 1], ah[mf], bl[2], bl[3]);
                    }
                }
            }
            __syncthreads();
        }

#pragma unroll
        for (int mf = 0; mf < 2; mf++) {
            int r0 = mw * 32 + mf * 16 + qlane;
            float is0 = invs[r0], is1 = invs[r0 + 8];
            int gi0 = i0 + r0, gi1 = gi0 + 8;
#pragma unroll
            for (int nf = 0; nf < 4; nf++) {
                addcorr(acc2[mf][nf], cor2[mf][nf]);
                int f = q * 128 + nw * 32 + nf * 8 + plane;
                if (gi0 < NI) {
                    float2 v = make_float2(acc2[mf][nf][0] * is0, acc2[mf][nf][1] * is0);
                    *reinterpret_cast<float2*>(out + ((size_t)b * NI + gi0) * FD + f) = v;
                }
                if (gi1 < NI) {
                    float2 v = make_float2(acc2[mf][nf][2] * is1, acc2[mf][nf][3] * is1);
                    *reinterpret_cast<float2*>(out + ((size_t)b * NI + gi1) * FD + f) = v;
                }
            }
        }
    }
}

// ---------------------------------------------------------------------------
extern "C" void kernel_launch(void* const* d_in, const int* in_sizes, int n_in,
                              void* d_out, int out_size)
{
    const float* h_r  = (const float*)d_in[0];  // (256, 512, 196)
    const float* vecs = (const float*)d_in[1];  // (1000, 300)
    const float* w_g  = (const float*)d_in[2];  // (300, 512)
    float* out = (float*)d_out;                 // (256, 1000, 512)

    cudaFuncSetAttribute(fused_mma, cudaFuncAttributeMaxDynamicSharedMemorySize, SMEM_REQ);

    qgemm16<<<dim3(4, NIPAD / 8), 128>>>(vecs, w_g);
    hsplit<<<dim3(7, 16, NB), dim3(32, 8)>>>(h_r);
    fused_mma<<<dim3(NIPAD / 128, NB), 512, SMEM_REQ>>>(out);
}

// round 7
// speedup vs baseline: 1.1292x; 1.1292x over previous
#include <cuda_runtime.h>
#include <cuda_fp16.h>
#include <cstdint>
#include <math.h>

#define FD 512
#define RD 196
#define RP 224
#define VDIM 300
#define NI 1000
#define NIPAD 1024
#define NB 256

// ---- smem byte map ----
#define G1_STAGE 56320
#define G1_QH 0
#define G1_QL 10240
#define G1_BH 20480
#define G1_BL 38400
#define P_H   0
#define P_L   59392
#define PSTR  464
#define G2_BASE  118784
#define G2_STAGE 8704
#define G2_PITCH 272
#define RED_M 153600
#define RED_S 155648
#define INV_S 157696
#define SMEM_REQ 158720

__device__ __align__(16) __half g_qh[NIPAD * FD];
__device__ __align__(16) __half g_ql[NIPAD * FD];
__device__ __align__(16) __half g_th[(size_t)NB * RP * FD];  // Ht [b][r][f]
__device__ __align__(16) __half g_tl[(size_t)NB * RP * FD];

// ---------------- PTX helpers ----------------
__device__ __forceinline__ uint32_t smem_u32(const void* p) {
    uint32_t a;
    asm("{ .reg .u64 t; cvta.to.shared.u64 t, %1; cvt.u32.u64 %0, t; }" : "=r"(a) : "l"(p));
    return a;
}
__device__ __forceinline__ void cpa16(uint32_t d, const void* s) {
    asm volatile("cp.async.cg.shared.global [%0], [%1], 16;" :: "r"(d), "l"(s));
}
#define CP_COMMIT() asm volatile("cp.async.commit_group;")
__device__ __forceinline__ void ldsm4(uint32_t* r, uint32_t a) {
    asm volatile("ldmatrix.sync.aligned.m8n8.x4.shared.b16 {%0,%1,%2,%3},[%4];"
        : "=r"(r[0]), "=r"(r[1]), "=r"(r[2]), "=r"(r[3]) : "r"(a));
}
__device__ __forceinline__ void ldsm4t(uint32_t* r, uint32_t a) {
    asm volatile("ldmatrix.sync.aligned.m8n8.x4.trans.shared.b16 {%0,%1,%2,%3},[%4];"
        : "=r"(r[0]), "=r"(r[1]), "=r"(r[2]), "=r"(r[3]) : "r"(a));
}
__device__ __forceinline__ void ldsm2(uint32_t* r, uint32_t a) {
    asm volatile("ldmatrix.sync.aligned.m8n8.x2.shared.b16 {%0,%1},[%2];"
        : "=r"(r[0]), "=r"(r[1]) : "r"(a));
}
__device__ __forceinline__ void mma_f32(float* d, const uint32_t* a, uint32_t b0, uint32_t b1) {
    asm volatile("mma.sync.aligned.m16n8k16.row.col.f32.f16.f16.f32 "
        "{%0,%1,%2,%3},{%4,%5,%6,%7},{%8,%9},{%0,%1,%2,%3};"
        : "+f"(d[0]), "+f"(d[1]), "+f"(d[2]), "+f"(d[3])
        : "r"(a[0]), "r"(a[1]), "r"(a[2]), "r"(a[3]), "r"(b0), "r"(b1));
}
__device__ __forceinline__ void mma_f16(uint32_t* d, const uint32_t* a, uint32_t b0, uint32_t b1) {
    asm volatile("mma.sync.aligned.m16n8k16.row.col.f16.f16.f16.f16 "
        "{%0,%1},{%2,%3,%4,%5},{%6,%7},{%0,%1};"
        : "+r"(d[0]), "+r"(d[1])
        : "r"(a[0]), "r"(a[1]), "r"(a[2]), "r"(a[3]), "r"(b0), "r"(b1));
}
__device__ __forceinline__ void split16(float v, __half& h, __half& l) {
    h = __float2half_rn(v);
    l = __float2half_rn(v - __half2float(h));
}
__device__ __forceinline__ uint32_t pack2(__half a, __half b) {
    __half2 t = __halves2half2(a, b);
    return *reinterpret_cast<uint32_t*>(&t);
}
__device__ __forceinline__ void addcorr(float* a4, const uint32_t* c2) {
    float2 f0 = __half22float2(*reinterpret_cast<const __half2*>(&c2[0]));
    float2 f1 = __half22float2(*reinterpret_cast<const __half2*>(&c2[1]));
    a4[0] += f0.x; a4[1] += f0.y; a4[2] += f1.x; a4[3] += f1.y;
}

// ---------------- prep 1: q = vecs @ w_g -> fp16 hi/lo ----------------
// grid (4, 32): 32 i-rows x 128 f-cols per block -> 128 blocks, 4x less w_g L2 traffic
__global__ __launch_bounds__(128) void qgemm16(
    const float* __restrict__ vecs, const float* __restrict__ w_g)
{
    __shared__ float vs[32][VDIM];
    const int f = blockIdx.x * 128 + threadIdx.x;
    const int i0 = blockIdx.y * 32;
    for (int e = threadIdx.x; e < 32 * VDIM; e += 128) {
        int ii = e / VDIM, v = e % VDIM, i = i0 + ii;
        vs[ii][v] = (i < NI) ? vecs[i * VDIM + v] : 0.0f;
    }
    __syncthreads();
    float acc[32];
#pragma unroll
    for (int ii = 0; ii < 32; ii++) acc[ii] = 0.0f;
#pragma unroll 2
    for (int v = 0; v < VDIM; v++) {
        float w = w_g[v * FD + f];
#pragma unroll
        for (int ii = 0; ii < 32; ii++) acc[ii] += vs[ii][v] * w;
    }
#pragma unroll
    for (int ii = 0; ii < 32; ii++) {
        __half h, l; split16(acc[ii], h, l);
        size_t o = (size_t)(i0 + ii) * FD + f;
        g_qh[o] = h; g_ql[o] = l;
    }
}

// ---------------- prep 2: split + transpose H -> g_th/g_tl ----------------
__global__ __launch_bounds__(256) void hsplit(const float* __restrict__ h)
{
    __shared__ float t[32][33];
    const int b = blockIdx.z, f0 = blockIdx.y * 32, r0 = blockIdx.x * 32;
    const int tx = threadIdx.x, ty = threadIdx.y;
#pragma unroll
    for (int s = 0; s < 4; s++) {
        int fl = ty + 8 * s, r = r0 + tx;
        t[fl][tx] = (r < RD) ? h[((size_t)b * FD + f0 + fl) * RD + r] : 0.0f;
    }
    __syncthreads();
#pragma unroll
    for (int s = 0; s < 4; s++) {
        int rl = ty + 8 * s;
        float v = t[tx][rl];
        __half hi, lo; split16(v, hi, lo);
        size_t o = ((size_t)b * RP + r0 + rl) * FD + f0 + tx;
        g_th[o] = hi; g_tl[o] = lo;
    }
}

// ---------------- stage loaders (cp.async), 256 threads ----------------
__device__ __forceinline__ void issue_g1(uint32_t sb,
    const __half* qh, const __half* ql, const __half* th, const __half* tl,
    int c, int tid)
{
    const int ko = c * 32;
    for (int t = tid; t < 512; t += 256) {
        int row = t >> 2, cc = t & 3;
        uint32_t d = sb + G1_QH + row * 80 + cc * 16;
        cpa16(d, qh + row * FD + ko + cc * 8);
        cpa16(d + (G1_QL - G1_QH), ql + row * FD + ko + cc * 8);
    }
    for (int t = tid; t < 896; t += 256) {
        int row = t >> 2, cc = t & 3;
        uint32_t d = sb + G1_BH + row * 80 + cc * 16;
        cpa16(d, th + row * FD + ko + cc * 8);
        cpa16(d + (G1_BL - G1_BH), tl + row * FD + ko + cc * 8);
    }
}
// GEMM2: stage 32 r-rows x 128 f-cols, HI ONLY, from g_th; pitch 272
__device__ __forceinline__ void issue_g2(uint32_t sb,
    const __half* th, int q, int kc, int tid)
{
    const int ro = kc * 32, fo = q * 128;
    for (int t = tid; t < 512; t += 256) {
        int row = t >> 4, cc = t & 15;
        cpa16(sb + row * G2_PITCH + cc * 16, th + (size_t)(ro + row) * FD + fo + cc * 8);
    }
}

// ---------------- main fused kernel: 256 threads, 8 warps (2x4) ----------------
__global__ __launch_bounds__(256, 1) void fused_mma(float* __restrict__ out)
{
    extern __shared__ char sm[];
    const uint32_t sbase = smem_u32(sm);
    float* redm = reinterpret_cast<float*>(sm + RED_M);
    float* reds = reinterpret_cast<float*>(sm + RED_S);
    float* invs = reinterpret_cast<float*>(sm + INV_S);

    const int tid = threadIdx.x, lane = tid & 31, wid = tid >> 5;
    const int mw = wid >> 2, nw = wid & 3;
    const int b = blockIdx.y, i0 = blockIdx.x * 128;

    const __half* qh = g_qh + (size_t)i0 * FD;
    const __half* ql = g_ql + (size_t)i0 * FD;
    const __half* th = g_th + (size_t)b * RP * FD;
    const __half* tl = g_tl + (size_t)b * RP * FD;

    const int arow = (lane & 7) + ((lane >> 3) & 1) * 8;
    const int acg  = (lane >> 4) * 16;

    // ======== GEMM1: C[128 i][224 r], K=512; warp tile 64 x 56 ========
    float acc[4][7][4];
    uint32_t cor[4][7][2];
#pragma unroll
    for (int mf = 0; mf < 4; mf++)
#pragma unroll
        for (int nf = 0; nf < 7; nf++) {
#pragma unroll
            for (int e = 0; e < 4; e++) acc[mf][nf][e] = 0.0f;
            cor[mf][nf][0] = 0u; cor[mf][nf][1] = 0u;
        }

    issue_g1(sbase, qh, ql, th, tl, 0, tid);
    CP_COMMIT();
    for (int c = 0; c < 16; c++) {
        const uint32_t st = sbase + (uint32_t)(c & 1) * G1_STAGE;
        if (c < 15) {
            issue_g1(sbase + (uint32_t)((c + 1) & 1) * G1_STAGE, qh, ql, th, tl, c + 1, tid);
            CP_COMMIT();
            asm volatile("cp.async.wait_group 1;");
        } else {
            asm volatile("cp.async.wait_group 0;");
        }
        __syncthreads();
#pragma unroll
        for (int kk = 0; kk < 2; kk++) {
            uint32_t ah[4][4], al[4][4];
#pragma unroll
            for (int mf = 0; mf < 4; mf++) {
                uint32_t ad = st + G1_QH + (uint32_t)(mw * 64 + mf * 16 + arow) * 80 + kk * 32 + acg;
                ldsm4(ah[mf], ad);
                ldsm4(al[mf], ad + (G1_QL - G1_QH));
            }
#pragma unroll
            for (int p = 0; p < 3; p++) {
                uint32_t bd = st + G1_BH + (uint32_t)(nw * 56 + p * 16 + arow) * 80 + kk * 32 + acg;
                uint32_t bh[4], bl[4];
                ldsm4(bh, bd);
                ldsm4(bl, bd + (G1_BL - G1_BH));
#pragma unroll
                for (int mf = 0; mf < 4; mf++) {
                    mma_f32(acc[mf][2 * p],     ah[mf], bh[0], bh[2]);
                    mma_f32(acc[mf][2 * p + 1], ah[mf], bh[1], bh[3]);
                    mma_f16(cor[mf][2 * p],     al[mf], bh[0], bh[2]);
                    mma_f16(cor[mf][2 * p + 1], al[mf], bh[1], bh[3]);
                    mma_f16(cor[mf][2 * p],     ah[mf], bl[0], bl[2]);
                    mma_f16(cor[mf][2 * p + 1], ah[mf], bl[1], bl[3]);
                }
            }
            {
                uint32_t bd = st + G1_BH + (uint32_t)(nw * 56 + 48 + (lane & 7)) * 80
                              + kk * 32 + ((lane >> 3) & 1) * 16;
                uint32_t bh[2], bl[2];
                ldsm2(bh, bd);
                ldsm2(bl, bd + (G1_BL - G1_BH));
#pragma unroll
                for (int mf = 0; mf < 4; mf++) {
                    mma_f32(acc[mf][6], ah[mf], bh[0], bh[1]);
                    mma_f16(cor[mf][6], al[mf], bh[0], bh[1]);
                    mma_f16(cor[mf][6], ah[mf], bl[0], bl[1]);
                }
            }
        }
        __syncthreads();
    }
#pragma unroll
    for (int mf = 0; mf < 4; mf++)
#pragma unroll
        for (int nf = 0; nf < 7; nf++) addcorr(acc[mf][nf], cor[mf][nf]);

    // ======== softmax over r ========
    const int qlane = lane >> 2, plane = 2 * (lane & 3);
#pragma unroll
    for (int mf = 0; mf < 4; mf++)
#pragma unroll
        for (int hh = 0; hh < 2; hh++) {
            float m = -INFINITY;
#pragma unroll
            for (int nf = 0; nf < 7; nf++)
#pragma unroll
                for (int e = 0; e < 2; e++) {
                    int col = nw * 56 + nf * 8 + plane + e;
                    if (col < RD) m = fmaxf(m, acc[mf][nf][2 * hh + e]);
                }
            m = fmaxf(m, __shfl_xor_sync(0xffffffffu, m, 1));
            m = fmaxf(m, __shfl_xor_sync(0xffffffffu, m, 2));
            if ((lane & 3) == 0) {
                int row = mw * 64 + mf * 16 + qlane + hh * 8;
                redm[row * 4 + nw] = m;
            }
        }
    __syncthreads();
#pragma unroll
    for (int mf = 0; mf < 4; mf++)
#pragma unroll
        for (int hh = 0; hh < 2; hh++) {
            int row = mw * 64 + mf * 16 + qlane + hh * 8;
            float m = fmaxf(fmaxf(redm[row * 4], redm[row * 4 + 1]),
                            fmaxf(redm[row * 4 + 2], redm[row * 4 + 3]));
            float s = 0.0f;
#pragma unroll
            for (int nf = 0; nf < 7; nf++) {
                float v0 = 0.0f, v1 = 0.0f;
                int col = nw * 56 + nf * 8 + plane;
                if (col     < RD) { v0 = __expf(acc[mf][nf][2 * hh]     - m); s += v0; }
                if (col + 1 < RD) { v1 = __expf(acc[mf][nf][2 * hh + 1] - m); s += v1; }
                __half h0, l0, h1, l1;
                split16(v0, h0, l0); split16(v1, h1, l1);
                uint32_t off = (uint32_t)row * PSTR + (uint32_t)col * 2;
                *reinterpret_cast<uint32_t*>(sm + P_H + off) = pack2(h0, h1);
                *reinterpret_cast<uint32_t*>(sm + P_L + off) = pack2(l0, l1);
            }
            s += __shfl_xor_sync(0xffffffffu, s, 1);
            s += __shfl_xor_sync(0xffffffffu, s, 2);
            if ((lane & 3) == 0) reds[row * 4 + nw] = s;
        }
    __syncthreads();
    if (wid < 4) {
        int row = wid * 32 + lane;
        float t = reds[row * 4] + reds[row * 4 + 1] + reds[row * 4 + 2] + reds[row * 4 + 3];
        invs[row] = 1.0f / t;
    }
    __syncthreads();

    // ======== GEMM2: E[128 i][512 f], K=224; B hi only ========
    const int brow = lane & 15;
    const int bcg  = (lane >> 4) * 16;
    for (int q = 0; q < 4; q++) {
        float acc2[4][4][4];
        uint32_t cor2[4][4][2];
#pragma unroll
        for (int mf = 0; mf < 4; mf++)
#pragma unroll
            for (int nf = 0; nf < 4; nf++) {
#pragma unroll
                for (int e = 0; e < 4; e++) acc2[mf][nf][e] = 0.0f;
                cor2[mf][nf][0] = 0u; cor2[mf][nf][1] = 0u;
            }

        issue_g2(sbase + G2_BASE, th, q, 0, tid);
        CP_COMMIT();
        for (int kc = 0; kc < 7; kc++) {
            const uint32_t st = sbase + G2_BASE + (uint32_t)(kc & 1) * G2_STAGE;
            if (kc < 6) {
                issue_g2(sbase + G2_BASE + (uint32_t)((kc + 1) & 1) * G2_STAGE, th, q, kc + 1, tid);
                CP_COMMIT();
                asm volatile("cp.async.wait_group 1;");
            } else {
                asm volatile("cp.async.wait_group 0;");
            }
            __syncthreads();
#pragma unroll
            for (int kk = 0; kk < 2; kk++) {
                uint32_t ah[4][4], al[4][4];
#pragma unroll
                for (int mf = 0; mf < 4; mf++) {
                    uint32_t ad = sbase + P_H + (uint32_t)(mw * 64 + mf * 16 + arow) * PSTR
                                  + (uint32_t)(kc * 64 + kk * 32) + acg;
                    ldsm4(ah[mf], ad);
                    ldsm4(al[mf], ad + (P_L - P_H));
                }
#pragma unroll
                for (int p = 0; p < 2; p++) {
                    uint32_t bd = st + (uint32_t)(kk * 16 + brow) * G2_PITCH
                                  + (uint32_t)(nw * 64 + p * 32) + bcg;
                    uint32_t bh[4];
                    ldsm4t(bh, bd);
#pragma unroll
                    for (int mf = 0; mf < 4; mf++) {
                        mma_f32(acc2[mf][2 * p],     ah[mf], bh[0], bh[1]);
                        mma_f32(acc2[mf][2 * p + 1], ah[mf], bh[2], bh[3]);
                        mma_f16(cor2[mf][2 * p],     al[mf], bh[0], bh[1]);
                        mma_f16(cor2[mf][2 * p + 1], al[mf], bh[2], bh[3]);
                    }
                }
            }
            __syncthreads();
        }

#pragma unroll
        for (int mf = 0; mf < 4; mf++) {
            int r0 = mw * 64 + mf * 16 + qlane;
            float is0 = invs[r0], is1 = invs[r0 + 8];
            int gi0 = i0 + r0, gi1 = gi0 + 8;
#pragma unroll
            for (int nf = 0; nf < 4; nf++) {
                addcorr(acc2[mf][nf], cor2[mf][nf]);
                int f = q * 128 + nw * 32 + nf * 8 + plane;
                if (gi0 < NI) {
                    float2 v = make_float2(acc2[mf][nf][0] * is0, acc2[mf][nf][1] * is0);
                    *reinterpret_cast<float2*>(out + ((size_t)b * NI + gi0) * FD + f) = v;
                }
                if (gi1 < NI) {
                    float2 v = make_float2(acc2[mf][nf][2] * is1, acc2[mf][nf][3] * is1);
                    *reinterpret_cast<float2*>(out + ((size_t)b * NI + gi1) * FD + f) = v;
                }
            }
        }
    }
}

// ---------------------------------------------------------------------------
extern "C" void kernel_launch(void* const* d_in, const int* in_sizes, int n_in,
                              void* d_out, int out_size)
{
    const float* h_r  = (const float*)d_in[0];  // (256, 512, 196)
    const float* vecs = (const float*)d_in[1];  // (1000, 300)
    const float* w_g  = (const float*)d_in[2];  // (300, 512)
    float* out = (float*)d_out;                 // (256, 1000, 512)

    cudaFuncSetAttribute(fused_mma, cudaFuncAttributeMaxDynamicSharedMemorySize, SMEM_REQ);

    qgemm16<<<dim3(4, NIPAD / 32), 128>>>(vecs, w_g);
    hsplit<<<dim3(7, 16, NB), dim3(32, 8)>>>(h_r);
    fused_mma<<<dim3(NIPAD / 128, NB), 256, SMEM_REQ>>>(out);
}

// round 8
// speedup vs baseline: 1.2968x; 1.1484x over previous
#include <cuda_runtime.h>
#include <cuda_fp16.h>
#include <cstdint>
#include <math.h>

#define FD 512
#define RD 196
#define RP 224
#define VDIM 300
#define NI 1000
#define NIPAD 1024
#define NB 256

// ---- smem byte map ----
#define G1_STAGE 56320
#define G1_QH 0
#define G1_QL 10240
#define G1_BH 20480
#define G1_BL 38400
#define P_H   0
#define PSTR  464
#define G2_BASE  118784
#define G2_STAGE 8704
#define G2_PITCH 272
#define RED_M 153600
#define RED_S 155648
#define INV_S 157696
#define SMEM_REQ 158720

__device__ __align__(16) __half g_qh[NIPAD * FD];
__device__ __align__(16) __half g_ql[NIPAD * FD];
__device__ __align__(16) __half g_th[(size_t)NB * RP * FD];  // Ht [b][r][f]
__device__ __align__(16) __half g_tl[(size_t)NB * RP * FD];

// ---------------- PTX helpers ----------------
__device__ __forceinline__ uint32_t smem_u32(const void* p) {
    uint32_t a;
    asm("{ .reg .u64 t; cvta.to.shared.u64 t, %1; cvt.u32.u64 %0, t; }" : "=r"(a) : "l"(p));
    return a;
}
__device__ __forceinline__ void cpa16(uint32_t d, const void* s) {
    asm volatile("cp.async.cg.shared.global [%0], [%1], 16;" :: "r"(d), "l"(s));
}
#define CP_COMMIT() asm volatile("cp.async.commit_group;")
__device__ __forceinline__ void ldsm4(uint32_t* r, uint32_t a) {
    asm volatile("ldmatrix.sync.aligned.m8n8.x4.shared.b16 {%0,%1,%2,%3},[%4];"
        : "=r"(r[0]), "=r"(r[1]), "=r"(r[2]), "=r"(r[3]) : "r"(a));
}
__device__ __forceinline__ void ldsm4t(uint32_t* r, uint32_t a) {
    asm volatile("ldmatrix.sync.aligned.m8n8.x4.trans.shared.b16 {%0,%1,%2,%3},[%4];"
        : "=r"(r[0]), "=r"(r[1]), "=r"(r[2]), "=r"(r[3]) : "r"(a));
}
__device__ __forceinline__ void ldsm2(uint32_t* r, uint32_t a) {
    asm volatile("ldmatrix.sync.aligned.m8n8.x2.shared.b16 {%0,%1},[%2];"
        : "=r"(r[0]), "=r"(r[1]) : "r"(a));
}
__device__ __forceinline__ void mma_f32(float* d, const uint32_t* a, uint32_t b0, uint32_t b1) {
    asm volatile("mma.sync.aligned.m16n8k16.row.col.f32.f16.f16.f32 "
        "{%0,%1,%2,%3},{%4,%5,%6,%7},{%8,%9},{%0,%1,%2,%3};"
        : "+f"(d[0]), "+f"(d[1]), "+f"(d[2]), "+f"(d[3])
        : "r"(a[0]), "r"(a[1]), "r"(a[2]), "r"(a[3]), "r"(b0), "r"(b1));
}
__device__ __forceinline__ void mma_f16(uint32_t* d, const uint32_t* a, uint32_t b0, uint32_t b1) {
    asm volatile("mma.sync.aligned.m16n8k16.row.col.f16.f16.f16.f16 "
        "{%0,%1},{%2,%3,%4,%5},{%6,%7},{%0,%1};"
        : "+r"(d[0]), "+r"(d[1])
        : "r"(a[0]), "r"(a[1]), "r"(a[2]), "r"(a[3]), "r"(b0), "r"(b1));
}
__device__ __forceinline__ void split16(float v, __half& h, __half& l) {
    h = __float2half_rn(v);
    l = __float2half_rn(v - __half2float(h));
}
__device__ __forceinline__ uint32_t pack2(__half a, __half b) {
    __half2 t = __halves2half2(a, b);
    return *reinterpret_cast<uint32_t*>(&t);
}
__device__ __forceinline__ void addcorr(float* a4, const uint32_t* c2) {
    float2 f0 = __half22float2(*reinterpret_cast<const __half2*>(&c2[0]));
    float2 f1 = __half22float2(*reinterpret_cast<const __half2*>(&c2[1]));
    a4[0] += f0.x; a4[1] += f0.y; a4[2] += f1.x; a4[3] += f1.y;
}

// ---------------- prep 1: q = vecs @ w_g -> fp16 hi/lo ----------------
// grid (4, 128): 8 i-rows x 128 f-cols per block (round-5 config, 42us)
__global__ __launch_bounds__(128) void qgemm16(
    const float* __restrict__ vecs, const float* __restrict__ w_g)
{
    __shared__ float vs[8][VDIM];
    const int f = blockIdx.x * 128 + threadIdx.x;
    const int i0 = blockIdx.y * 8;
    for (int e = threadIdx.x; e < 8 * VDIM; e += 128) {
        int ii = e / VDIM, v = e % VDIM, i = i0 + ii;
        vs[ii][v] = (i < NI) ? vecs[i * VDIM + v] : 0.0f;
    }
    __syncthreads();
    float acc[8];
#pragma unroll
    for (int ii = 0; ii < 8; ii++) acc[ii] = 0.0f;
#pragma unroll 4
    for (int v = 0; v < VDIM; v++) {
        float w = w_g[v * FD + f];
#pragma unroll
        for (int ii = 0; ii < 8; ii++) acc[ii] += vs[ii][v] * w;
    }
#pragma unroll
    for (int ii = 0; ii < 8; ii++) {
        __half h, l; split16(acc[ii], h, l);
        size_t o = (size_t)(i0 + ii) * FD + f;
        g_qh[o] = h; g_ql[o] = l;
    }
}

// ---------------- prep 2: split + transpose H -> g_th/g_tl ----------------
__global__ __launch_bounds__(256) void hsplit(const float* __restrict__ h)
{
    __shared__ float t[32][33];
    const int b = blockIdx.z, f0 = blockIdx.y * 32, r0 = blockIdx.x * 32;
    const int tx = threadIdx.x, ty = threadIdx.y;
#pragma unroll
    for (int s = 0; s < 4; s++) {
        int fl = ty + 8 * s, r = r0 + tx;
        t[fl][tx] = (r < RD) ? h[((size_t)b * FD + f0 + fl) * RD + r] : 0.0f;
    }
    __syncthreads();
#pragma unroll
    for (int s = 0; s < 4; s++) {
        int rl = ty + 8 * s;
        float v = t[tx][rl];
        __half hi, lo; split16(v, hi, lo);
        size_t o = ((size_t)b * RP + r0 + rl) * FD + f0 + tx;
        g_th[o] = hi; g_tl[o] = lo;
    }
}

// ---------------- stage loaders (cp.async), 256 threads ----------------
__device__ __forceinline__ void issue_g1(uint32_t sb,
    const __half* qh, const __half* ql, const __half* th, const __half* tl,
    int c, int tid)
{
    const int ko = c * 32;
    for (int t = tid; t < 512; t += 256) {
        int row = t >> 2, cc = t & 3;
        uint32_t d = sb + G1_QH + row * 80 + cc * 16;
        cpa16(d, qh + row * FD + ko + cc * 8);
        cpa16(d + (G1_QL - G1_QH), ql + row * FD + ko + cc * 8);
    }
    for (int t = tid; t < 896; t += 256) {
        int row = t >> 2, cc = t & 3;
        uint32_t d = sb + G1_BH + row * 80 + cc * 16;
        cpa16(d, th + row * FD + ko + cc * 8);
        cpa16(d + (G1_BL - G1_BH), tl + row * FD + ko + cc * 8);
    }
}
// GEMM2: stage 32 r-rows x 128 f-cols, HI ONLY, from g_th; pitch 272
__device__ __forceinline__ void issue_g2(uint32_t sb,
    const __half* th, int q, int kc, int tid)
{
    const int ro = kc * 32, fo = q * 128;
    for (int t = tid; t < 512; t += 256) {
        int row = t >> 4, cc = t & 15;
        cpa16(sb + row * G2_PITCH + cc * 16, th + (size_t)(ro + row) * FD + fo + cc * 8);
    }
}

// ---------------- main fused kernel: 256 threads, 8 warps (2x4) ----------------
__global__ __launch_bounds__(256, 1) void fused_mma(float* __restrict__ out)
{
    extern __shared__ char sm[];
    const uint32_t sbase = smem_u32(sm);
    float* redm = reinterpret_cast<float*>(sm + RED_M);
    float* reds = reinterpret_cast<float*>(sm + RED_S);
    float* invs = reinterpret_cast<float*>(sm + INV_S);

    const int tid = threadIdx.x, lane = tid & 31, wid = tid >> 5;
    const int mw = wid >> 2, nw = wid & 3;
    const int b = blockIdx.y, i0 = blockIdx.x * 128;

    const __half* qh = g_qh + (size_t)i0 * FD;
    const __half* ql = g_ql + (size_t)i0 * FD;
    const __half* th = g_th + (size_t)b * RP * FD;
    const __half* tl = g_tl + (size_t)b * RP * FD;

    const int arow = (lane & 7) + ((lane >> 3) & 1) * 8;
    const int acg  = (lane >> 4) * 16;

    // ======== GEMM1: C[128 i][224 r], K=512; warp tile 64 x 56 ========
    float acc[4][7][4];
    uint32_t cor[4][7][2];
#pragma unroll
    for (int mf = 0; mf < 4; mf++)
#pragma unroll
        for (int nf = 0; nf < 7; nf++) {
#pragma unroll
            for (int e = 0; e < 4; e++) acc[mf][nf][e] = 0.0f;
            cor[mf][nf][0] = 0u; cor[mf][nf][1] = 0u;
        }

    issue_g1(sbase, qh, ql, th, tl, 0, tid);
    CP_COMMIT();
    for (int c = 0; c < 16; c++) {
        const uint32_t st = sbase + (uint32_t)(c & 1) * G1_STAGE;
        if (c < 15) {
            issue_g1(sbase + (uint32_t)((c + 1) & 1) * G1_STAGE, qh, ql, th, tl, c + 1, tid);
            CP_COMMIT();
            asm volatile("cp.async.wait_group 1;");
        } else {
            asm volatile("cp.async.wait_group 0;");
        }
        __syncthreads();
#pragma unroll
        for (int kk = 0; kk < 2; kk++) {
            uint32_t ah[4][4], al[4][4];
#pragma unroll
            for (int mf = 0; mf < 4; mf++) {
                uint32_t ad = st + G1_QH + (uint32_t)(mw * 64 + mf * 16 + arow) * 80 + kk * 32 + acg;
                ldsm4(ah[mf], ad);
                ldsm4(al[mf], ad + (G1_QL - G1_QH));
            }
#pragma unroll
            for (int p = 0; p < 3; p++) {
                uint32_t bd = st + G1_BH + (uint32_t)(nw * 56 + p * 16 + arow) * 80 + kk * 32 + acg;
                uint32_t bh[4], bl[4];
                ldsm4(bh, bd);
                ldsm4(bl, bd + (G1_BL - G1_BH));
#pragma unroll
                for (int mf = 0; mf < 4; mf++) {
                    mma_f32(acc[mf][2 * p],     ah[mf], bh[0], bh[2]);
                    mma_f32(acc[mf][2 * p + 1], ah[mf], bh[1], bh[3]);
                    mma_f16(cor[mf][2 * p],     al[mf], bh[0], bh[2]);
                    mma_f16(cor[mf][2 * p + 1], al[mf], bh[1], bh[3]);
                    mma_f16(cor[mf][2 * p],     ah[mf], bl[0], bl[2]);
                    mma_f16(cor[mf][2 * p + 1], ah[mf], bl[1], bl[3]);
                }
            }
            {
                uint32_t bd = st + G1_BH + (uint32_t)(nw * 56 + 48 + (lane & 7)) * 80
                              + kk * 32 + ((lane >> 3) & 1) * 16;
                uint32_t bh[2], bl[2];
                ldsm2(bh, bd);
                ldsm2(bl, bd + (G1_BL - G1_BH));
#pragma unroll
                for (int mf = 0; mf < 4; mf++) {
                    mma_f32(acc[mf][6], ah[mf], bh[0], bh[1]);
                    mma_f16(cor[mf][6], al[mf], bh[0], bh[1]);
                    mma_f16(cor[mf][6], ah[mf], bl[0], bl[1]);
                }
            }
        }
        __syncthreads();
    }
#pragma unroll
    for (int mf = 0; mf < 4; mf++)
#pragma unroll
        for (int nf = 0; nf < 7; nf++) addcorr(acc[mf][nf], cor[mf][nf]);

    // ======== softmax over r ========
    const int qlane = lane >> 2, plane = 2 * (lane & 3);
#pragma unroll
    for (int mf = 0; mf < 4; mf++)
#pragma unroll
        for (int hh = 0; hh < 2; hh++) {
            float m = -INFINITY;
#pragma unroll
            for (int nf = 0; nf < 7; nf++)
#pragma unroll
                for (int e = 0; e < 2; e++) {
                    int col = nw * 56 + nf * 8 + plane + e;
                    if (col < RD) m = fmaxf(m, acc[mf][nf][2 * hh + e]);
                }
            m = fmaxf(m, __shfl_xor_sync(0xffffffffu, m, 1));
            m = fmaxf(m, __shfl_xor_sync(0xffffffffu, m, 2));
            if ((lane & 3) == 0) {
                int row = mw * 64 + mf * 16 + qlane + hh * 8;
                redm[row * 4 + nw] = m;
            }
        }
    __syncthreads();
#pragma unroll
    for (int mf = 0; mf < 4; mf++)
#pragma unroll
        for (int hh = 0; hh < 2; hh++) {
            int row = mw * 64 + mf * 16 + qlane + hh * 8;
            float m = fmaxf(fmaxf(redm[row * 4], redm[row * 4 + 1]),
                            fmaxf(redm[row * 4 + 2], redm[row * 4 + 3]));
            float s = 0.0f;
#pragma unroll
            for (int nf = 0; nf < 7; nf++) {
                float v0 = 0.0f, v1 = 0.0f;
                int col = nw * 56 + nf * 8 + plane;
                if (col     < RD) { v0 = __expf(acc[mf][nf][2 * hh]     - m); s += v0; }
                if (col + 1 < RD) { v1 = __expf(acc[mf][nf][2 * hh + 1] - m); s += v1; }
                uint32_t off = (uint32_t)row * PSTR + (uint32_t)col * 2;
                *reinterpret_cast<uint32_t*>(sm + P_H + off) =
                    pack2(__float2half_rn(v0), __float2half_rn(v1));
            }
            s += __shfl_xor_sync(0xffffffffu, s, 1);
            s += __shfl_xor_sync(0xffffffffu, s, 2);
            if ((lane & 3) == 0) reds[row * 4 + nw] = s;
        }
    __syncthreads();
    if (wid < 4) {
        int row = wid * 32 + lane;
        float t = reds[row * 4] + reds[row * 4 + 1] + reds[row * 4 + 2] + reds[row * 4 + 3];
        invs[row] = 1.0f / t;
    }
    __syncthreads();

    // ======== GEMM2: E[128 i][512 f], K=224; P hi-only, B hi-only ========
    const int brow = lane & 15;
    const int bcg  = (lane >> 4) * 16;
    for (int q = 0; q < 4; q++) {
        float acc2[4][4][4];
#pragma unroll
        for (int mf = 0; mf < 4; mf++)
#pragma unroll
            for (int nf = 0; nf < 4; nf++)
#pragma unroll
                for (int e = 0; e < 4; e++) acc2[mf][nf][e] = 0.0f;

        issue_g2(sbase + G2_BASE, th, q, 0, tid);
        CP_COMMIT();
        for (int kc = 0; kc < 7; kc++) {
            const uint32_t st = sbase + G2_BASE + (uint32_t)(kc & 1) * G2_STAGE;
            if (kc < 6) {
                issue_g2(sbase + G2_BASE + (uint32_t)((kc + 1) & 1) * G2_STAGE, th, q, kc + 1, tid);
                CP_COMMIT();
                asm volatile("cp.async.wait_group 1;");
            } else {
                asm volatile("cp.async.wait_group 0;");
            }
            __syncthreads();
#pragma unroll
            for (int kk = 0; kk < 2; kk++) {
                uint32_t ah[4][4];
#pragma unroll
                for (int mf = 0; mf < 4; mf++) {
                    uint32_t ad = sbase + P_H + (uint32_t)(mw * 64 + mf * 16 + arow) * PSTR
                                  + (uint32_t)(kc * 64 + kk * 32) + acg;
                    ldsm4(ah[mf], ad);
                }
#pragma unroll
                for (int p = 0; p < 2; p++) {
                    uint32_t bd = st + (uint32_t)(kk * 16 + brow) * G2_PITCH
                                  + (uint32_t)(nw * 64 + p * 32) + bcg;
                    uint32_t bh[4];
                    ldsm4t(bh, bd);
#pragma unroll
                    for (int mf = 0; mf < 4; mf++) {
                        mma_f32(acc2[mf][2 * p],     ah[mf], bh[0], bh[1]);
                        mma_f32(acc2[mf][2 * p + 1], ah[mf], bh[2], bh[3]);
                    }
                }
            }
            __syncthreads();
        }

#pragma unroll
        for (int mf = 0; mf < 4; mf++) {
            int r0 = mw * 64 + mf * 16 + qlane;
            float is0 = invs[r0], is1 = invs[r0 + 8];
            int gi0 = i0 + r0, gi1 = gi0 + 8;
#pragma unroll
            for (int nf = 0; nf < 4; nf++) {
                int f = q * 128 + nw * 32 + nf * 8 + plane;
                if (gi0 < NI) {
                    float2 v = make_float2(acc2[mf][nf][0] * is0, acc2[mf][nf][1] * is0);
                    *reinterpret_cast<float2*>(out + ((size_t)b * NI + gi0) * FD + f) = v;
                }
                if (gi1 < NI) {
                    float2 v = make_float2(acc2[mf][nf][2] * is1, acc2[mf][nf][3] * is1);
                    *reinterpret_cast<float2*>(out + ((size_t)b * NI + gi1) * FD + f) = v;
                }
            }
        }
    }
}

// ---------------------------------------------------------------------------
extern "C" void kernel_launch(void* const* d_in, const int* in_sizes, int n_in,
                              void* d_out, int out_size)
{
    const float* h_r  = (const float*)d_in[0];  // (256, 512, 196)
    const float* vecs = (const float*)d_in[1];  // (1000, 300)
    const float* w_g  = (const float*)d_in[2];  // (300, 512)
    float* out = (float*)d_out;                 // (256, 1000, 512)

    cudaFuncSetAttribute(fused_mma, cudaFuncAttributeMaxDynamicSharedMemorySize, SMEM_REQ);

    qgemm16<<<dim3(4, NIPAD / 8), 128>>>(vecs, w_g);
    hsplit<<<dim3(7, 16, NB), dim3(32, 8)>>>(h_r);
    fused_mma<<<dim3(NIPAD / 128, NB), 256, SMEM_REQ>>>(out);
}